// round 1
// baseline (speedup 1.0000x reference)
#include <cuda_runtime.h>
#include <math.h>

#define DD 1024
#define BSZ 256

// Scratch (device globals — no allocation allowed in kernel_launch)
__device__ float g_h[BSZ * DD];
__device__ float g_logits[BSZ * DD];
__device__ float g_text2[BSZ * DD];
__device__ float g_pre_txt[BSZ * DD];
__device__ float g_pimgb[BSZ * DD];   // pre_img + rb1

// ---------------------------------------------------------------------------
// Small GEMM: C[MxN] = (A[MxK] @ B[KxN]) [+ bias] [relu]
// 64x64 tile, BK=16, 256 threads, 4x4 per thread.
// ---------------------------------------------------------------------------
template <bool RELU, bool HAS_BIAS>
__global__ void __launch_bounds__(256)
small_gemm(const float* __restrict__ A, const float* __restrict__ B,
           const float* __restrict__ bias, float* __restrict__ C,
           int M, int N, int K)
{
    __shared__ float As[16][68];   // transposed [k][m], padded
    __shared__ float Bs[16][64];   // [k][n]

    const int t  = threadIdx.x;
    const int m0 = blockIdx.y * 64;
    const int n0 = blockIdx.x * 64;
    const int tx = t & 15, ty = t >> 4;

    const int ar  = t >> 2;          // A row within tile (0..63)
    const int akv = (t & 3) * 4;     // A k-vector start (0,4,8,12)
    const int bk  = t >> 4;          // B k row (0..15)
    const int bnv = (t & 15) * 4;    // B n-vector start

    float acc[4][4] = {};

    for (int k0 = 0; k0 < K; k0 += 16) {
        float4 a4 = *(const float4*)(A + (size_t)(m0 + ar) * K + k0 + akv);
        float4 b4 = *(const float4*)(B + (size_t)(k0 + bk) * N + n0 + bnv);
        __syncthreads();
        As[akv + 0][ar] = a4.x;
        As[akv + 1][ar] = a4.y;
        As[akv + 2][ar] = a4.z;
        As[akv + 3][ar] = a4.w;
        *(float4*)(&Bs[bk][bnv]) = b4;
        __syncthreads();

        #pragma unroll
        for (int kk = 0; kk < 16; kk++) {
            float a[4], b[4];
            *(float4*)a = *(const float4*)(&As[kk][ty * 4]);
            *(float4*)b = *(const float4*)(&Bs[kk][tx * 4]);
            #pragma unroll
            for (int r = 0; r < 4; r++)
                #pragma unroll
                for (int c = 0; c < 4; c++)
                    acc[r][c] = fmaf(a[r], b[c], acc[r][c]);
        }
    }

    #pragma unroll
    for (int r = 0; r < 4; r++) {
        const int m = m0 + ty * 4 + r;
        #pragma unroll
        for (int c = 0; c < 4; c++) {
            const int n = n0 + tx * 4 + c;
            float v = acc[r][c];
            if (HAS_BIAS) v += bias[n];
            if (RELU) v = fmaxf(v, 0.0f);
            C[(size_t)m * N + n] = v;
        }
    }
}

// ---------------------------------------------------------------------------
// Row softmax over D followed by elementwise multiply with text:
//   out[row,k] = text[row,k] * softmax(logits[row,:])[k]
// One block (256 threads) per row.
// ---------------------------------------------------------------------------
__global__ void __launch_bounds__(256)
softmax_mul(const float* __restrict__ logits, const float* __restrict__ text,
            float* __restrict__ out)
{
    const int row = blockIdx.x;
    const int t   = threadIdx.x;
    const float* l = logits + (size_t)row * DD;

    __shared__ float smax[8];
    __shared__ float ssum[8];

    // --- row max ---
    float m = -1e30f;
    #pragma unroll
    for (int k = t; k < DD; k += 256) m = fmaxf(m, l[k]);
    #pragma unroll
    for (int o = 16; o > 0; o >>= 1)
        m = fmaxf(m, __shfl_xor_sync(0xffffffffu, m, o));
    if ((t & 31) == 0) smax[t >> 5] = m;
    __syncthreads();
    float rowmax = smax[0];
    #pragma unroll
    for (int w = 1; w < 8; w++) rowmax = fmaxf(rowmax, smax[w]);

    // --- sum of exp ---
    float s = 0.0f;
    #pragma unroll
    for (int k = t; k < DD; k += 256) s += expf(l[k] - rowmax);
    #pragma unroll
    for (int o = 16; o > 0; o >>= 1)
        s += __shfl_xor_sync(0xffffffffu, s, o);
    if ((t & 31) == 0) ssum[t >> 5] = s;
    __syncthreads();
    float tot = 0.0f;
    #pragma unroll
    for (int w = 0; w < 8; w++) tot += ssum[w];
    const float inv = 1.0f / tot;

    const float* tr = text + (size_t)row * DD;
    float* orow = out + (size_t)row * DD;
    #pragma unroll
    for (int k = t; k < DD; k += 256)
        orow[k] = tr[k] * (expf(l[k] - rowmax) * inv);
}

// ---------------------------------------------------------------------------
// Big fused GEMM:
//   m = i*256 + j  (i = text row, j = image row), M = 65536, N = K = 1024
//   A[m,k] = relu(pre_txt[i,k] + pimgb[j,k])        (synthesized on the fly)
//   out[m,n] = A[m,:] @ rw2[:,n] + image[j,n] + rb2[n]
// 128x128 tile, BK=8, 256 threads, 8x8 per thread.
// Each 128-row tile has a SINGLE i (tiles are 128-aligned within a 256-row
// i-group), so pre_txt is one broadcast row per tile.
// ---------------------------------------------------------------------------
__global__ void __launch_bounds__(256)
big_gemm(const float* __restrict__ pre_txt, const float* __restrict__ pimgb,
         const float* __restrict__ rw2, const float* __restrict__ image,
         const float* __restrict__ rb2, float* __restrict__ out)
{
    __shared__ float As[8][132];   // transposed [k][m], padded (conflict-free stores)
    __shared__ float Bs[8][132];   // [k][n], padded

    const int t  = threadIdx.x;
    const int n0 = blockIdx.x * 128;
    const int m0 = blockIdx.y * 128;
    const int i  = m0 >> 8;        // constant across the tile
    const int j0 = m0 & 255;       // 0 or 128

    const float* pt = pre_txt + (size_t)i * DD;
    const int tx = t & 15, ty = t >> 4;

    const int ar  = t >> 1;                 // A row in tile (0..127)
    const int akv = (t & 1) * 4;            // A k-vec (0 or 4)
    const int bk  = t >> 5;                 // B k row (0..7)
    const int bnv = (t & 31) * 4;           // B n-vec

    const float* pib_row = pimgb + (size_t)(j0 + ar) * DD + akv;
    const float* b_row   = rw2 + (size_t)bk * DD + n0 + bnv;

    float acc[8][8] = {};

    for (int k0 = 0; k0 < DD; k0 += 8) {
        float4 p  = *(const float4*)(pt + k0 + akv);
        float4 q  = *(const float4*)(pib_row + k0);
        float4 b4 = *(const float4*)(b_row + (size_t)k0 * DD);
        __syncthreads();
        As[akv + 0][ar] = fmaxf(p.x + q.x, 0.0f);
        As[akv + 1][ar] = fmaxf(p.y + q.y, 0.0f);
        As[akv + 2][ar] = fmaxf(p.z + q.z, 0.0f);
        As[akv + 3][ar] = fmaxf(p.w + q.w, 0.0f);
        *(float4*)(&Bs[bk][bnv]) = b4;
        __syncthreads();

        #pragma unroll
        for (int kk = 0; kk < 8; kk++) {
            float a[8], b[8];
            *(float4*)(a)     = *(const float4*)(&As[kk][ty * 4]);
            *(float4*)(a + 4) = *(const float4*)(&As[kk][64 + ty * 4]);
            *(float4*)(b)     = *(const float4*)(&Bs[kk][tx * 4]);
            *(float4*)(b + 4) = *(const float4*)(&Bs[kk][64 + tx * 4]);
            #pragma unroll
            for (int r = 0; r < 8; r++)
                #pragma unroll
                for (int c = 0; c < 8; c++)
                    acc[r][c] = fmaf(a[r], b[c], acc[r][c]);
        }
    }

    // Epilogue: + image[j] + rb2, vectorized stores
    #pragma unroll
    for (int r = 0; r < 8; r++) {
        const int lr = (r < 4) ? (ty * 4 + r) : (64 + ty * 4 + (r - 4));
        const size_t orow = (size_t)(m0 + lr) * DD;
        const float* img = image + (size_t)(j0 + lr) * DD;
        #pragma unroll
        for (int cp = 0; cp < 2; cp++) {
            const int lc = cp * 64 + tx * 4;
            const int cb = cp * 4;
            float4 im = *(const float4*)(img + n0 + lc);
            float4 rb = *(const float4*)(rb2 + n0 + lc);
            float4 o;
            o.x = acc[r][cb + 0] + im.x + rb.x;
            o.y = acc[r][cb + 1] + im.y + rb.y;
            o.z = acc[r][cb + 2] + im.z + rb.z;
            o.w = acc[r][cb + 3] + im.w + rb.w;
            *(float4*)(out + orow + n0 + lc) = o;
        }
    }
}

// ---------------------------------------------------------------------------
extern "C" void kernel_launch(void* const* d_in, const int* in_sizes, int n_in,
                              void* d_out, int out_size)
{
    const float* image = (const float*)d_in[0];
    const float* text  = (const float*)d_in[1];
    const float* aw1   = (const float*)d_in[2];
    const float* ab1   = (const float*)d_in[3];
    const float* aw2   = (const float*)d_in[4];
    const float* ab2   = (const float*)d_in[5];
    const float* rw1   = (const float*)d_in[6];
    const float* rb1   = (const float*)d_in[7];
    const float* rw2   = (const float*)d_in[8];
    const float* rb2   = (const float*)d_in[9];
    float* out = (float*)d_out;

    float *h_p, *logits_p, *text2_p, *pretxt_p, *pimgb_p;
    cudaGetSymbolAddress((void**)&h_p,      g_h);
    cudaGetSymbolAddress((void**)&logits_p, g_logits);
    cudaGetSymbolAddress((void**)&text2_p,  g_text2);
    cudaGetSymbolAddress((void**)&pretxt_p, g_pre_txt);
    cudaGetSymbolAddress((void**)&pimgb_p,  g_pimgb);

    dim3 blk(256);
    dim3 gs(DD / 64, BSZ / 64);   // (16, 4)

    // h = relu(text @ aw1 + ab1)
    small_gemm<true, true><<<gs, blk>>>(text, aw1, ab1, h_p, BSZ, DD, DD);
    // logits = h @ aw2 + ab2
    small_gemm<false, true><<<gs, blk>>>(h_p, aw2, ab2, logits_p, BSZ, DD, DD);
    // text2 = text * softmax(logits, axis=1)
    softmax_mul<<<BSZ, blk>>>(logits_p, text, text2_p);
    // pimgb = image @ rw1[:D] + rb1
    small_gemm<false, true><<<gs, blk>>>(image, rw1, rb1, pimgb_p, BSZ, DD, DD);
    // pre_txt = text2 @ rw1[D:]
    small_gemm<false, false><<<gs, blk>>>(text2_p, rw1 + (size_t)DD * DD, nullptr,
                                          pretxt_p, BSZ, DD, DD);
    // out[i*256+j, :] = image[j] + rb2 + relu(pre_txt[i] + pimgb[j]) @ rw2
    dim3 gb(DD / 128, (BSZ * BSZ) / 128);  // (8, 512)
    big_gemm<<<gb, blk>>>(pretxt_p, pimgb_p, rw2, image, rb2, out);
}

// round 2
// speedup vs baseline: 4.2125x; 4.2125x over previous
#include <cuda_runtime.h>
#include <cuda_bf16.h>
#include <math.h>

#define DD 1024
#define BSZ 256

// ---- scratch globals --------------------------------------------------------
__device__ float g_h[BSZ * DD];
__device__ float g_logits[BSZ * DD];
__device__ float g_text2[BSZ * DD];
__device__ __nv_bfloat16 g_pretxt_h[BSZ * DD];
__device__ __nv_bfloat16 g_pimgb_h[BSZ * DD];
__device__ __nv_bfloat16 g_rw2_h[DD * DD];

// ---------------------------------------------------------------------------
// 64x64-tile fp32 GEMM body (M=256, N=K=1024), optional relu/bias, optional
// bf16 output. Shared memory passed in (dynamic) so two instantiations can
// share one allocation in a z-batched kernel.
// ---------------------------------------------------------------------------
template <bool RELU, bool HAS_BIAS, bool BF16OUT>
__device__ __forceinline__ void gemm64_body(
    const float* __restrict__ A, const float* __restrict__ B,
    const float* __restrict__ bias, void* __restrict__ Cv, float* smem)
{
    float (*As)[68] = (float(*)[68])smem;            // 16 x 68
    float (*Bs)[64] = (float(*)[64])(smem + 16 * 68); // 16 x 64

    const int t  = threadIdx.x;
    const int m0 = blockIdx.y * 64;
    const int n0 = blockIdx.x * 64;
    const int tx = t & 15, ty = t >> 4;

    const int ar  = t >> 2;
    const int akv = (t & 3) * 4;
    const int bk  = t >> 4;
    const int bnv = (t & 15) * 4;

    float acc[4][4] = {};

    for (int k0 = 0; k0 < DD; k0 += 16) {
        float4 a4 = *(const float4*)(A + (size_t)(m0 + ar) * DD + k0 + akv);
        float4 b4 = *(const float4*)(B + (size_t)(k0 + bk) * DD + n0 + bnv);
        __syncthreads();
        As[akv + 0][ar] = a4.x;
        As[akv + 1][ar] = a4.y;
        As[akv + 2][ar] = a4.z;
        As[akv + 3][ar] = a4.w;
        *(float4*)(&Bs[bk][bnv]) = b4;
        __syncthreads();

        #pragma unroll
        for (int kk = 0; kk < 16; kk++) {
            float a[4], b[4];
            *(float4*)a = *(const float4*)(&As[kk][ty * 4]);
            *(float4*)b = *(const float4*)(&Bs[kk][tx * 4]);
            #pragma unroll
            for (int r = 0; r < 4; r++)
                #pragma unroll
                for (int c = 0; c < 4; c++)
                    acc[r][c] = fmaf(a[r], b[c], acc[r][c]);
        }
    }

    #pragma unroll
    for (int r = 0; r < 4; r++) {
        const int m = m0 + ty * 4 + r;
        #pragma unroll
        for (int c = 0; c < 4; c++) {
            const int n = n0 + tx * 4 + c;
            float v = acc[r][c];
            if (HAS_BIAS) v += bias[n];
            if (RELU) v = fmaxf(v, 0.0f);
            if (BF16OUT)
                ((__nv_bfloat16*)Cv)[(size_t)m * DD + n] = __float2bfloat16(v);
            else
                ((float*)Cv)[(size_t)m * DD + n] = v;
        }
    }
}

// z=0: h = relu(text@aw1+ab1)   z=1: pimgb_h = bf16(image@rw1[:D]+rb1)
__global__ void __launch_bounds__(256)
small_pair(const float* __restrict__ text, const float* __restrict__ aw1,
           const float* __restrict__ ab1, float* __restrict__ h,
           const float* __restrict__ image, const float* __restrict__ rw1,
           const float* __restrict__ rb1, __nv_bfloat16* __restrict__ pimgb)
{
    extern __shared__ float smem[];
    if (blockIdx.z == 0)
        gemm64_body<true, true, false>(text, aw1, ab1, h, smem);
    else
        gemm64_body<false, true, true>(image, rw1, rb1, pimgb, smem);
}

__global__ void __launch_bounds__(256)
small_logits(const float* __restrict__ h, const float* __restrict__ aw2,
             const float* __restrict__ ab2, float* __restrict__ logits)
{
    extern __shared__ float smem[];
    gemm64_body<false, true, false>(h, aw2, ab2, logits, smem);
}

__global__ void __launch_bounds__(256)
small_pretxt(const float* __restrict__ text2, const float* __restrict__ rw1b,
             __nv_bfloat16* __restrict__ pretxt)
{
    extern __shared__ float smem[];
    gemm64_body<false, false, true>(text2, rw1b, nullptr, pretxt, smem);
}

// ---------------------------------------------------------------------------
__global__ void __launch_bounds__(256)
convert_rw2(const float* __restrict__ in, __nv_bfloat16* __restrict__ out)
{
    const int idx = (blockIdx.x * 256 + threadIdx.x) * 4;
    float4 v = *(const float4*)(in + idx);
    __nv_bfloat16 o[4] = {
        __float2bfloat16(v.x), __float2bfloat16(v.y),
        __float2bfloat16(v.z), __float2bfloat16(v.w)};
    *(uint2*)(out + idx) = *(uint2*)o;
}

// ---------------------------------------------------------------------------
__global__ void __launch_bounds__(256)
softmax_mul(const float* __restrict__ logits, const float* __restrict__ text,
            float* __restrict__ out)
{
    const int row = blockIdx.x;
    const int t   = threadIdx.x;
    const float* l = logits + (size_t)row * DD;

    __shared__ float smax[8];
    __shared__ float ssum[8];

    float m = -1e30f;
    #pragma unroll
    for (int k = t; k < DD; k += 256) m = fmaxf(m, l[k]);
    #pragma unroll
    for (int o = 16; o > 0; o >>= 1)
        m = fmaxf(m, __shfl_xor_sync(0xffffffffu, m, o));
    if ((t & 31) == 0) smax[t >> 5] = m;
    __syncthreads();
    float rowmax = smax[0];
    #pragma unroll
    for (int w = 1; w < 8; w++) rowmax = fmaxf(rowmax, smax[w]);

    float s = 0.0f;
    #pragma unroll
    for (int k = t; k < DD; k += 256) s += expf(l[k] - rowmax);
    #pragma unroll
    for (int o = 16; o > 0; o >>= 1)
        s += __shfl_xor_sync(0xffffffffu, s, o);
    if ((t & 31) == 0) ssum[t >> 5] = s;
    __syncthreads();
    float tot = 0.0f;
    #pragma unroll
    for (int w = 0; w < 8; w++) tot += ssum[w];
    const float inv = 1.0f / tot;

    const float* tr = text + (size_t)row * DD;
    float* orow = out + (size_t)row * DD;
    #pragma unroll
    for (int k = t; k < DD; k += 256)
        orow[k] = tr[k] * (expf(l[k] - rowmax) * inv);
}

// ---------------------------------------------------------------------------
// Big GEMM on tensor cores (bf16 mma.sync, fp32 accumulate).
//   m = i*256 + j ; A[m,k] = relu(pretxt[i,k] + pimgb[j,k]) (bf16, on the fly)
//   out[m,n] = A[m,:] @ rw2[:,n] + image[j,n] + rb2[n]
// CTA tile 128x128, BK=32, 256 threads = 8 warps (2 m x 4 n), warp tile 64x32.
// ---------------------------------------------------------------------------
#define LDSM_X4(r0,r1,r2,r3,addr) \
    asm volatile("ldmatrix.sync.aligned.m8n8.x4.shared.b16 {%0,%1,%2,%3}, [%4];" \
        : "=r"(r0),"=r"(r1),"=r"(r2),"=r"(r3) : "r"(addr))
#define LDSM_X4_T(r0,r1,r2,r3,addr) \
    asm volatile("ldmatrix.sync.aligned.m8n8.x4.trans.shared.b16 {%0,%1,%2,%3}, [%4];" \
        : "=r"(r0),"=r"(r1),"=r"(r2),"=r"(r3) : "r"(addr))
#define MMA_BF16(d0,d1,d2,d3,a0,a1,a2,a3,b0,b1) \
    asm volatile("mma.sync.aligned.m16n8k16.row.col.f32.bf16.bf16.f32 " \
        "{%0,%1,%2,%3}, {%4,%5,%6,%7}, {%8,%9}, {%0,%1,%2,%3};" \
        : "+f"(d0),"+f"(d1),"+f"(d2),"+f"(d3) \
        : "r"(a0),"r"(a1),"r"(a2),"r"(a3),"r"(b0),"r"(b1))

__device__ __forceinline__ uint4 fuse_relu_bf16(uint4 p, uint4 t)
{
    const __nv_bfloat162 z = __float2bfloat162_rn(0.0f);
    uint4 r;
    const __nv_bfloat162* pp = (const __nv_bfloat162*)&p;
    const __nv_bfloat162* tt = (const __nv_bfloat162*)&t;
    __nv_bfloat162* rr = (__nv_bfloat162*)&r;
    #pragma unroll
    for (int q = 0; q < 4; q++)
        rr[q] = __hmax2(__hadd2(pp[q], tt[q]), z);
    return r;
}

__global__ void __launch_bounds__(256)
big_gemm_mma(const __nv_bfloat16* __restrict__ pretxt,
             const __nv_bfloat16* __restrict__ pimgb,
             const __nv_bfloat16* __restrict__ rw2,
             const float* __restrict__ image,
             const float* __restrict__ rb2,
             float* __restrict__ out)
{
    __shared__ __nv_bfloat16 As[128][40];   // [m][k], 80B rows (16B aligned)
    __shared__ __nv_bfloat16 Bs[32][136];   // [k][n], 272B rows (16B aligned)

    const int t    = threadIdx.x;
    const int lane = t & 31;
    const int warp = t >> 5;
    const int n0 = blockIdx.x * 128;
    const int m0 = blockIdx.y * 128;
    const int i  = m0 >> 8;
    const int j0 = m0 & 255;

    const int wm = (warp >> 2) * 64;   // 0 or 64
    const int wn = (warp & 3) * 32;    // 0..96

    // loader indices
    const int ar  = t >> 1;            // A row 0..127
    const int akv = (t & 1) * 16;      // 0 or 16
    const int br  = t >> 3;            // B row 0..31
    const int bnv = (t & 7) * 16;      // 0..112

    const __nv_bfloat16* ptrow = pretxt + (size_t)i * DD;
    const __nv_bfloat16* parow = pimgb + (size_t)(j0 + ar) * DD + akv;
    const __nv_bfloat16* pbrow = rw2 + (size_t)br * DD + n0 + bnv;

    // ldmatrix shared addresses (u32)
    const unsigned aBase = (unsigned)__cvta_generic_to_shared(
        &As[wm + ((lane >> 3) & 1) * 8 + (lane & 7)][(lane >> 4) * 8]);
    const unsigned bBase = (unsigned)__cvta_generic_to_shared(
        &Bs[((lane >> 3) & 1) * 8 + (lane & 7)][wn + (lane >> 4) * 8]);

    float acc[4][4][4] = {};  // [mt][nt][reg]

    uint4 pv0, pv1, tv0, tv1, bv0, bv1;
    // preload chunk 0
    pv0 = *(const uint4*)(parow);
    pv1 = *(const uint4*)(parow + 8);
    tv0 = *(const uint4*)(ptrow + akv);
    tv1 = *(const uint4*)(ptrow + akv + 8);
    bv0 = *(const uint4*)(pbrow);
    bv1 = *(const uint4*)(pbrow + 8);

    for (int k0 = 0; k0 < DD; k0 += 32) {
        __syncthreads();
        *(uint4*)(&As[ar][akv])     = fuse_relu_bf16(pv0, tv0);
        *(uint4*)(&As[ar][akv + 8]) = fuse_relu_bf16(pv1, tv1);
        *(uint4*)(&Bs[br][bnv])     = bv0;
        *(uint4*)(&Bs[br][bnv + 8]) = bv1;
        __syncthreads();

        if (k0 + 32 < DD) {  // prefetch next chunk while computing
            const int kn = k0 + 32;
            pv0 = *(const uint4*)(parow + kn);
            pv1 = *(const uint4*)(parow + kn + 8);
            tv0 = *(const uint4*)(ptrow + kn + akv);
            tv1 = *(const uint4*)(ptrow + kn + akv + 8);
            bv0 = *(const uint4*)(pbrow + (size_t)kn * DD);
            bv1 = *(const uint4*)(pbrow + (size_t)kn * DD + 8);
        }

        #pragma unroll
        for (int ks = 0; ks < 2; ks++) {
            const int kk = ks * 16;
            unsigned a[4][4];
            #pragma unroll
            for (int mt = 0; mt < 4; mt++)
                LDSM_X4(a[mt][0], a[mt][1], a[mt][2], a[mt][3],
                        aBase + mt * 16 * 80 + kk * 2);
            unsigned b[4][2];
            #pragma unroll
            for (int bt = 0; bt < 2; bt++)
                LDSM_X4_T(b[bt*2][0], b[bt*2][1], b[bt*2+1][0], b[bt*2+1][1],
                          bBase + kk * 272 + bt * 32);
            #pragma unroll
            for (int mt = 0; mt < 4; mt++)
                #pragma unroll
                for (int nt = 0; nt < 4; nt++)
                    MMA_BF16(acc[mt][nt][0], acc[mt][nt][1],
                             acc[mt][nt][2], acc[mt][nt][3],
                             a[mt][0], a[mt][1], a[mt][2], a[mt][3],
                             b[nt][0], b[nt][1]);
        }
    }

    // epilogue: + image[j] + rb2
    #pragma unroll
    for (int mt = 0; mt < 4; mt++) {
        const int rbase = wm + mt * 16 + (lane >> 2);
        #pragma unroll
        for (int half = 0; half < 2; half++) {
            const int r = rbase + half * 8;
            const float* img = image + (size_t)(j0 + r) * DD;
            const size_t orow = (size_t)(m0 + r) * DD;
            #pragma unroll
            for (int nt = 0; nt < 4; nt++) {
                const int c = n0 + wn + nt * 8 + (lane & 3) * 2;
                float2 im = *(const float2*)(img + c);
                float2 rb = *(const float2*)(rb2 + c);
                float2 o;
                o.x = acc[mt][nt][half * 2 + 0] + im.x + rb.x;
                o.y = acc[mt][nt][half * 2 + 1] + im.y + rb.y;
                *(float2*)(out + orow + c) = o;
            }
        }
    }
}

// ---------------------------------------------------------------------------
extern "C" void kernel_launch(void* const* d_in, const int* in_sizes, int n_in,
                              void* d_out, int out_size)
{
    const float* image = (const float*)d_in[0];
    const float* text  = (const float*)d_in[1];
    const float* aw1   = (const float*)d_in[2];
    const float* ab1   = (const float*)d_in[3];
    const float* aw2   = (const float*)d_in[4];
    const float* ab2   = (const float*)d_in[5];
    const float* rw1   = (const float*)d_in[6];
    const float* rb1   = (const float*)d_in[7];
    const float* rw2   = (const float*)d_in[8];
    const float* rb2   = (const float*)d_in[9];
    float* out = (float*)d_out;

    float *h_p, *logits_p, *text2_p;
    __nv_bfloat16 *pretxt_p, *pimgb_p, *rw2h_p;
    cudaGetSymbolAddress((void**)&h_p,      g_h);
    cudaGetSymbolAddress((void**)&logits_p, g_logits);
    cudaGetSymbolAddress((void**)&text2_p,  g_text2);
    cudaGetSymbolAddress((void**)&pretxt_p, g_pretxt_h);
    cudaGetSymbolAddress((void**)&pimgb_p,  g_pimgb_h);
    cudaGetSymbolAddress((void**)&rw2h_p,   g_rw2_h);

    const int smallSmem = (16 * 68 + 16 * 64) * sizeof(float);
    dim3 blk(256);

    // rw2 -> bf16 (independent of everything)
    convert_rw2<<<DD * DD / 1024, blk>>>(rw2, rw2h_p);
    // z=0: h = relu(text@aw1+ab1); z=1: pimgb = bf16(image@rw1[:D]+rb1)
    small_pair<<<dim3(16, 4, 2), blk, smallSmem>>>(
        text, aw1, ab1, h_p, image, rw1, rb1, pimgb_p);
    // logits = h @ aw2 + ab2
    small_logits<<<dim3(16, 4), blk, smallSmem>>>(h_p, aw2, ab2, logits_p);
    // text2 = text * softmax(logits)
    softmax_mul<<<BSZ, blk>>>(logits_p, text, text2_p);
    // pretxt = bf16(text2 @ rw1[D:])
    small_pretxt<<<dim3(16, 4), blk, smallSmem>>>(
        text2_p, rw1 + (size_t)DD * DD, pretxt_p);
    // big fused GEMM on tensor cores
    big_gemm_mma<<<dim3(8, 512), blk>>>(pretxt_p, pimgb_p, rw2h_p,
                                        image, rb2, out);
}

// round 4
// speedup vs baseline: 5.4604x; 1.2962x over previous
#include <cuda_runtime.h>
#include <cuda_bf16.h>
#include <math.h>
#include <stdint.h>

#define DD 1024
#define BSZ 256

// ---- scratch globals --------------------------------------------------------
__device__ float g_h[BSZ * DD];
__device__ float g_logits[BSZ * DD];
__device__ float g_text2[BSZ * DD];
__device__ __nv_bfloat16 g_pretxt_h[BSZ * DD];
__device__ __nv_bfloat16 g_pimgb_h[BSZ * DD];
__device__ __nv_bfloat16 g_rw2_h[DD * DD];   // rw2 bf16, [k][n] (same layout as fp32)

// ---- cp.async helpers ------------------------------------------------------
#define CP_ASYNC16(dst, src) \
    asm volatile("cp.async.cg.shared.global [%0], [%1], 16;" \
        :: "r"(dst), "l"(src) : "memory")
#define CP_COMMIT() asm volatile("cp.async.commit_group;" ::: "memory")
#define CP_WAIT0()  asm volatile("cp.async.wait_group 0;" ::: "memory")

// ============================================================================
// Small-chain fp32 GEMMs: 64x64 tile, BK=32, double-buffered SMEM,
// register prefetch, ONE __syncthreads per chunk.
// ============================================================================
template <bool RELU, bool HAS_BIAS, bool BF16OUT>
__device__ __forceinline__ void gemm64_body(
    const float* __restrict__ A, const float* __restrict__ B,
    const float* __restrict__ bias, void* __restrict__ Cv, float* smem)
{
    const int AS  = 32 * 68;       // A stage: [k][m] stride 68
    const int BS_ = 32 * 64;       // B stage: [k][n] stride 64
    const int STG = AS + BS_;

    const int t  = threadIdx.x;
    const int m0 = blockIdx.y * 64;
    const int n0 = blockIdx.x * 64;
    const int tx = t & 15, ty = t >> 4;

    // A loader: row = t&63 (0..63), k-group = (t>>6)*8 (0,8,16,24)
    const int ar  = t & 63;
    const int akv = (t >> 6) * 8;
    // B loader: k row = t>>3 (0..31), n-group = (t&7)*8
    const int bk  = t >> 3;
    const int bnv = (t & 7) * 8;

    const float* Arow = A + (size_t)(m0 + ar) * DD + akv;
    const float* Brow = B + (size_t)bk * DD + n0 + bnv;

    float4 a0, a1, b0, b1;
    // prologue: chunk 0
    a0 = *(const float4*)(Arow);
    a1 = *(const float4*)(Arow + 4);
    b0 = *(const float4*)(Brow);
    b1 = *(const float4*)(Brow + 4);
    {
        float* Ad = smem;
        float* Bd = smem + AS;
        Ad[(akv + 0) * 68 + ar] = a0.x; Ad[(akv + 1) * 68 + ar] = a0.y;
        Ad[(akv + 2) * 68 + ar] = a0.z; Ad[(akv + 3) * 68 + ar] = a0.w;
        Ad[(akv + 4) * 68 + ar] = a1.x; Ad[(akv + 5) * 68 + ar] = a1.y;
        Ad[(akv + 6) * 68 + ar] = a1.z; Ad[(akv + 7) * 68 + ar] = a1.w;
        *(float4*)(&Bd[bk * 64 + bnv])     = b0;
        *(float4*)(&Bd[bk * 64 + bnv + 4]) = b1;
    }
    __syncthreads();

    float acc[4][4] = {};

    for (int c = 0; c < 32; c++) {
        const int s = c & 1;
        const float* As = smem + s * STG;
        const float* Bs = smem + s * STG + AS;
        const int kn = (c + 1) * 32;

        if (c < 31) {   // prefetch next chunk (latency overlaps compute below)
            a0 = *(const float4*)(Arow + kn);
            a1 = *(const float4*)(Arow + kn + 4);
            b0 = *(const float4*)(Brow + (size_t)kn * DD);
            b1 = *(const float4*)(Brow + (size_t)kn * DD + 4);
        }

        #pragma unroll
        for (int kk = 0; kk < 32; kk++) {
            float a[4], b[4];
            *(float4*)a = *(const float4*)(&As[kk * 68 + ty * 4]);
            *(float4*)b = *(const float4*)(&Bs[kk * 64 + tx * 4]);
            #pragma unroll
            for (int r = 0; r < 4; r++)
                #pragma unroll
                for (int cc = 0; cc < 4; cc++)
                    acc[r][cc] = fmaf(a[r], b[cc], acc[r][cc]);
        }

        if (c < 31) {   // store prefetched chunk into the other stage
            float* Ad = smem + (s ^ 1) * STG;
            float* Bd = Ad + AS;
            Ad[(akv + 0) * 68 + ar] = a0.x; Ad[(akv + 1) * 68 + ar] = a0.y;
            Ad[(akv + 2) * 68 + ar] = a0.z; Ad[(akv + 3) * 68 + ar] = a0.w;
            Ad[(akv + 4) * 68 + ar] = a1.x; Ad[(akv + 5) * 68 + ar] = a1.y;
            Ad[(akv + 6) * 68 + ar] = a1.z; Ad[(akv + 7) * 68 + ar] = a1.w;
            *(float4*)(&Bd[bk * 64 + bnv])     = b0;
            *(float4*)(&Bd[bk * 64 + bnv + 4]) = b1;
        }
        __syncthreads();
    }

    #pragma unroll
    for (int r = 0; r < 4; r++) {
        const int m = m0 + ty * 4 + r;
        #pragma unroll
        for (int c = 0; c < 4; c++) {
            const int n = n0 + tx * 4 + c;
            float v = acc[r][c];
            if (HAS_BIAS) v += bias[n];
            if (RELU) v = fmaxf(v, 0.0f);
            if (BF16OUT)
                ((__nv_bfloat16*)Cv)[(size_t)m * DD + n] = __float2bfloat16(v);
            else
                ((float*)Cv)[(size_t)m * DD + n] = v;
        }
    }
}

#define SMALL_SMEM (2 * (32 * 68 + 32 * 64) * (int)sizeof(float))

__global__ void __launch_bounds__(256)
small_pair(const float* __restrict__ text, const float* __restrict__ aw1,
           const float* __restrict__ ab1, float* __restrict__ h,
           const float* __restrict__ image, const float* __restrict__ rw1,
           const float* __restrict__ rb1, __nv_bfloat16* __restrict__ pimgb)
{
    extern __shared__ float smemf[];
    if (blockIdx.z == 0)
        gemm64_body<true, true, false>(text, aw1, ab1, h, smemf);
    else
        gemm64_body<false, true, true>(image, rw1, rb1, pimgb, smemf);
}

__global__ void __launch_bounds__(256)
small_logits(const float* __restrict__ h, const float* __restrict__ aw2,
             const float* __restrict__ ab2, float* __restrict__ logits)
{
    extern __shared__ float smemf[];
    gemm64_body<false, true, false>(h, aw2, ab2, logits, smemf);
}

__global__ void __launch_bounds__(256)
small_pretxt(const float* __restrict__ text2, const float* __restrict__ rw1b,
             __nv_bfloat16* __restrict__ pretxt)
{
    extern __shared__ float smemf[];
    gemm64_body<false, false, true>(text2, rw1b, nullptr, pretxt, smemf);
}

// ---------------------------------------------------------------------------
__global__ void __launch_bounds__(256)
convert_rw2(const float* __restrict__ in, __nv_bfloat16* __restrict__ out)
{
    const int idx = (blockIdx.x * 256 + threadIdx.x) * 4;
    float4 v = *(const float4*)(in + idx);
    __nv_bfloat16 o[4] = {
        __float2bfloat16(v.x), __float2bfloat16(v.y),
        __float2bfloat16(v.z), __float2bfloat16(v.w)};
    *(uint2*)(out + idx) = *(uint2*)o;
}

// ---------------------------------------------------------------------------
__global__ void __launch_bounds__(256)
softmax_mul(const float* __restrict__ logits, const float* __restrict__ text,
            float* __restrict__ out)
{
    const int row = blockIdx.x;
    const int t   = threadIdx.x;
    const float* l = logits + (size_t)row * DD;
    __shared__ float smax[8];
    __shared__ float ssum[8];

    float m = -1e30f;
    #pragma unroll
    for (int k = t; k < DD; k += 256) m = fmaxf(m, l[k]);
    #pragma unroll
    for (int o = 16; o > 0; o >>= 1)
        m = fmaxf(m, __shfl_xor_sync(0xffffffffu, m, o));
    if ((t & 31) == 0) smax[t >> 5] = m;
    __syncthreads();
    float rowmax = smax[0];
    #pragma unroll
    for (int w = 1; w < 8; w++) rowmax = fmaxf(rowmax, smax[w]);

    float s = 0.0f;
    #pragma unroll
    for (int k = t; k < DD; k += 256) s += expf(l[k] - rowmax);
    #pragma unroll
    for (int o = 16; o > 0; o >>= 1)
        s += __shfl_xor_sync(0xffffffffu, s, o);
    if ((t & 31) == 0) ssum[t >> 5] = s;
    __syncthreads();
    float tot = 0.0f;
    #pragma unroll
    for (int w = 0; w < 8; w++) tot += ssum[w];
    const float inv = 1.0f / tot;

    const float* tr = text + (size_t)row * DD;
    float* orow = out + (size_t)row * DD;
    #pragma unroll
    for (int k = t; k < DD; k += 256)
        orow[k] = tr[k] * (expf(l[k] - rowmax) * inv);
}

// ============================================================================
// Big GEMM on mma.sync (bf16, fp32 accum) — double-buffered, cp.async for B.
//   m = i*256 + j ; A[m,k] = relu(pretxt[i,k] + pimgb[j,k])  (on the fly)
//   out[m,n] = A[m,:] @ rw2[:,n] + image[j,n] + rb2[n]
// CTA tile 128x128, BK=32, 256 threads = 8 warps (2m x 4n), warp tile 64x32.
// ============================================================================
#define LDSM_X4(r0,r1,r2,r3,addr) \
    asm volatile("ldmatrix.sync.aligned.m8n8.x4.shared.b16 {%0,%1,%2,%3}, [%4];" \
        : "=r"(r0),"=r"(r1),"=r"(r2),"=r"(r3) : "r"(addr))
#define LDSM_X4_T(r0,r1,r2,r3,addr) \
    asm volatile("ldmatrix.sync.aligned.m8n8.x4.trans.shared.b16 {%0,%1,%2,%3}, [%4];" \
        : "=r"(r0),"=r"(r1),"=r"(r2),"=r"(r3) : "r"(addr))
#define MMA_BF16(d0,d1,d2,d3,a0,a1,a2,a3,b0,b1) \
    asm volatile("mma.sync.aligned.m16n8k16.row.col.f32.bf16.bf16.f32 " \
        "{%0,%1,%2,%3}, {%4,%5,%6,%7}, {%8,%9}, {%0,%1,%2,%3};" \
        : "+f"(d0),"+f"(d1),"+f"(d2),"+f"(d3) \
        : "r"(a0),"r"(a1),"r"(a2),"r"(a3),"r"(b0),"r"(b1))

__device__ __forceinline__ uint4 fuse_relu_bf16(uint4 p, uint4 t)
{
    const __nv_bfloat162 z = __float2bfloat162_rn(0.0f);
    uint4 r;
    const __nv_bfloat162* pp = (const __nv_bfloat162*)&p;
    const __nv_bfloat162* tt = (const __nv_bfloat162*)&t;
    __nv_bfloat162* rr = (__nv_bfloat162*)&r;
    #pragma unroll
    for (int q = 0; q < 4; q++)
        rr[q] = __hmax2(__hadd2(pp[q], tt[q]), z);
    return r;
}

__global__ void __launch_bounds__(256, 2)
big_gemm_mma(const __nv_bfloat16* __restrict__ pretxt,
             const __nv_bfloat16* __restrict__ pimgb,
             const __nv_bfloat16* __restrict__ rw2,
             const float* __restrict__ image,
             const float* __restrict__ rb2,
             float* __restrict__ out)
{
    __shared__ __nv_bfloat16 As[2][128][40];   // [m][k], 80B rows
    __shared__ __nv_bfloat16 Bs[2][32][136];   // [k][n], 272B rows

    const uint32_t ASTG = 128 * 40 * 2;        // 10240
    const uint32_t BSTG = 32 * 136 * 2;        // 8704

    const int t    = threadIdx.x;
    const int lane = t & 31;
    const int warp = t >> 5;
    const int n0 = blockIdx.x * 128;
    const int m0 = blockIdx.y * 128;
    const int i  = m0 >> 8;
    const int j0 = m0 & 255;

    const int wm = (warp >> 2) * 64;
    const int wn = (warp & 3) * 32;

    const int ar  = t >> 1;            // A row 0..127
    const int akv = (t & 1) * 16;      // 0 or 16
    const int br  = t >> 3;            // B k row 0..31
    const int bnv = (t & 7) * 16;      // 0..112

    const __nv_bfloat16* ptrow = pretxt + (size_t)i * DD;
    const __nv_bfloat16* parow = pimgb + (size_t)(j0 + ar) * DD + akv;
    const __nv_bfloat16* pbrow = rw2 + (size_t)br * DD + n0 + bnv;

    const uint32_t bdst0 = (uint32_t)__cvta_generic_to_shared(&Bs[0][br][bnv]);

    const uint32_t aBase = (uint32_t)__cvta_generic_to_shared(
        &As[0][wm + ((lane >> 3) & 1) * 8 + (lane & 7)][(lane >> 4) * 8]);
    const uint32_t bBase = (uint32_t)__cvta_generic_to_shared(
        &Bs[0][((lane >> 3) & 1) * 8 + (lane & 7)][wn + (lane >> 4) * 8]);

    float acc[4][4][4] = {};

    // --- prologue: chunk 0 into stage 0 ---
    CP_ASYNC16(bdst0,      pbrow);
    CP_ASYNC16(bdst0 + 16, pbrow + 8);
    CP_COMMIT();
    {
        uint4 pv0 = *(const uint4*)(parow);
        uint4 pv1 = *(const uint4*)(parow + 8);
        uint4 tv0 = *(const uint4*)(ptrow + akv);
        uint4 tv1 = *(const uint4*)(ptrow + akv + 8);
        *(uint4*)(&As[0][ar][akv])     = fuse_relu_bf16(pv0, tv0);
        *(uint4*)(&As[0][ar][akv + 8]) = fuse_relu_bf16(pv1, tv1);
    }
    CP_WAIT0();
    __syncthreads();

    uint4 pv0, pv1, tv0, tv1;
    for (int c = 0; c < 32; c++) {
        const int s  = c & 1;
        const int ns = s ^ 1;
        const int kn = (c + 1) * 32;

        if (c < 31) {   // issue next-chunk loads NOW; latency overlaps compute
            CP_ASYNC16(bdst0 + ns * BSTG,      pbrow + (size_t)kn * DD);
            CP_ASYNC16(bdst0 + ns * BSTG + 16, pbrow + (size_t)kn * DD + 8);
            CP_COMMIT();
            pv0 = *(const uint4*)(parow + kn);
            pv1 = *(const uint4*)(parow + kn + 8);
            tv0 = *(const uint4*)(ptrow + kn + akv);
            tv1 = *(const uint4*)(ptrow + kn + akv + 8);
        }

        // ---- compute on stage s ----
        const uint32_t aB = aBase + s * ASTG;
        const uint32_t bB = bBase + s * BSTG;
        #pragma unroll
        for (int ks = 0; ks < 2; ks++) {
            const int kk = ks * 16;
            unsigned a[4][4];
            #pragma unroll
            for (int mt = 0; mt < 4; mt++)
                LDSM_X4(a[mt][0], a[mt][1], a[mt][2], a[mt][3],
                        aB + mt * 16 * 80 + kk * 2);
            unsigned b[4][2];
            #pragma unroll
            for (int bt = 0; bt < 2; bt++)
                LDSM_X4_T(b[bt*2][0], b[bt*2][1], b[bt*2+1][0], b[bt*2+1][1],
                          bB + kk * 272 + bt * 32);
            #pragma unroll
            for (int mt = 0; mt < 4; mt++)
                #pragma unroll
                for (int nt = 0; nt < 4; nt++)
                    MMA_BF16(acc[mt][nt][0], acc[mt][nt][1],
                             acc[mt][nt][2], acc[mt][nt][3],
                             a[mt][0], a[mt][1], a[mt][2], a[mt][3],
                             b[nt][0], b[nt][1]);
        }

        if (c < 31) {   // store prefetched A into next stage; wait B cp.async
            *(uint4*)(&As[ns][ar][akv])     = fuse_relu_bf16(pv0, tv0);
            *(uint4*)(&As[ns][ar][akv + 8]) = fuse_relu_bf16(pv1, tv1);
            CP_WAIT0();
        }
        __syncthreads();
    }

    // ---- epilogue: + image[j] + rb2 ----
    #pragma unroll
    for (int mt = 0; mt < 4; mt++) {
        const int rbase = wm + mt * 16 + (lane >> 2);
        #pragma unroll
        for (int half = 0; half < 2; half++) {
            const int r = rbase + half * 8;
            const float* img = image + (size_t)(j0 + r) * DD;
            const size_t orow = (size_t)(m0 + r) * DD;
            #pragma unroll
            for (int nt = 0; nt < 4; nt++) {
                const int col = n0 + wn + nt * 8 + (lane & 3) * 2;
                float2 im = *(const float2*)(img + col);
                float2 rb = *(const float2*)(rb2 + col);
                float2 o;
                o.x = acc[mt][nt][half * 2 + 0] + im.x + rb.x;
                o.y = acc[mt][nt][half * 2 + 1] + im.y + rb.y;
                *(float2*)(out + orow + col) = o;
            }
        }
    }
}

// ---------------------------------------------------------------------------
extern "C" void kernel_launch(void* const* d_in, const int* in_sizes, int n_in,
                              void* d_out, int out_size)
{
    const float* image = (const float*)d_in[0];
    const float* text  = (const float*)d_in[1];
    const float* aw1   = (const float*)d_in[2];
    const float* ab1   = (const float*)d_in[3];
    const float* aw2   = (const float*)d_in[4];
    const float* ab2   = (const float*)d_in[5];
    const float* rw1   = (const float*)d_in[6];
    const float* rb1   = (const float*)d_in[7];
    const float* rw2   = (const float*)d_in[8];
    const float* rb2   = (const float*)d_in[9];
    float* out = (float*)d_out;

    float *h_p, *logits_p, *text2_p;
    __nv_bfloat16 *pretxt_p, *pimgb_p, *rw2h_p;
    cudaGetSymbolAddress((void**)&h_p,      g_h);
    cudaGetSymbolAddress((void**)&logits_p, g_logits);
    cudaGetSymbolAddress((void**)&text2_p,  g_text2);
    cudaGetSymbolAddress((void**)&pretxt_p, g_pretxt_h);
    cudaGetSymbolAddress((void**)&pimgb_p,  g_pimgb_h);
    cudaGetSymbolAddress((void**)&rw2h_p,   g_rw2_h);

    dim3 blk(256);

    // rw2 -> bf16 (independent of the chain)
    convert_rw2<<<DD * DD / 1024, blk>>>(rw2, rw2h_p);
    // z=0: h = relu(text@aw1+ab1); z=1: pimgb = bf16(image@rw1[:D]+rb1)
    small_pair<<<dim3(16, 4, 2), blk, SMALL_SMEM>>>(
        text, aw1, ab1, h_p, image, rw1, rb1, pimgb_p);
    // logits = h @ aw2 + ab2
    small_logits<<<dim3(16, 4), blk, SMALL_SMEM>>>(h_p, aw2, ab2, logits_p);
    // text2 = text * softmax(logits)
    softmax_mul<<<BSZ, blk>>>(logits_p, text, text2_p);
    // pretxt = bf16(text2 @ rw1[D:])
    small_pretxt<<<dim3(16, 4), blk, SMALL_SMEM>>>(
        text2_p, rw1 + (size_t)DD * DD, pretxt_p);
    // big fused GEMM on tensor cores (mma.sync)
    big_gemm_mma<<<dim3(8, 512), blk>>>(pretxt_p, pimgb_p, rw2h_p,
                                        image, rb2, out);
}